// round 1
// baseline (speedup 1.0000x reference)
#include <cuda_runtime.h>

// Problem shapes (fixed by the dataset): B=8, N=4096 -> T=32768 tokens,
// K=4096 codes, D=256. Derived at runtime where cheap, hardcoded for scratch.
#define DDIM 256
#define TMAX 32768
#define KMAX 4096
#define TM 64
#define KT 64
#define NTHREADS 256

// Scratch (allocation-free rule: __device__ globals)
__device__ float g_esq[KMAX];             // ||e_k||^2
__device__ float g_et[(size_t)DDIM * KMAX];   // embed transposed [D][K]
__device__ float g_xt[(size_t)DDIM * TMAX];   // x transposed     [D][T]

// ---------------------------------------------------------------------------
// e_sq: sequential left-to-right fp32 sum (mimic reduction as closely as we can)
__global__ void esq_kernel(const float* __restrict__ embed, int K) {
    int k = blockIdx.x * blockDim.x + threadIdx.x;
    if (k >= K) return;
    const float* row = embed + (size_t)k * DDIM;
    float s = 0.f;
    for (int d = 0; d < DDIM; ++d)
        s = __fadd_rn(s, __fmul_rn(row[d], row[d]));
    g_esq[k] = s;
}

// ---------------------------------------------------------------------------
// Generic [R][C] -> [C][R] transpose, 32x32 tiles, R,C multiples of 32
__global__ void transpose_kernel(const float* __restrict__ in,
                                 float* __restrict__ out, int R, int C) {
    __shared__ float tile[32][33];
    int c0 = blockIdx.x * 32, r0 = blockIdx.y * 32;
    int tx = threadIdx.x;
    for (int i = threadIdx.y; i < 32; i += 8)
        tile[i][tx] = in[(size_t)(r0 + i) * C + (c0 + tx)];
    __syncthreads();
    for (int i = threadIdx.y; i < 32; i += 8)
        out[(size_t)(c0 + i) * R + (r0 + tx)] = tile[tx][i];
}

// ---------------------------------------------------------------------------
// Fused distance-GEMM + argmax + gather.
// CTA: 64 tokens x all K (in 64-code chunks). 256 threads as 16x16 grid,
// each thread owns a 4(token)x4(code) microtile. Tiles stored d-major in smem
// (rows of 64 floats): a-reads broadcast within half-warp, b-reads spread
// across 16 lanes -> conflict-free LDS.128.
__global__ __launch_bounds__(NTHREADS, 1)
void vq_argmax_kernel(const float* __restrict__ xt,    // [D][T]
                      const float* __restrict__ et,    // [D][K]
                      const float* __restrict__ esq,   // [K]
                      const float* __restrict__ embed, // [K][D]
                      float* __restrict__ out_q,       // [T][D]
                      float* __restrict__ out_i,       // [T] (as float) or null
                      int T, int K) {
    extern __shared__ float sm[];
    float* Xs    = sm;                       // [D][TM]
    float* Es    = sm + DDIM * TM;           // [D][KT]
    float* s_xsq = sm + 2 * DDIM * TM;       // [TM]
    int*   s_bi  = (int*)(s_xsq + TM);       // [TM]

    const int tid = threadIdx.x;
    const int tx = tid & 15, ty = tid >> 4;
    const int t0 = blockIdx.x * TM;

    // Load X tile (coalesced from pre-transposed g_xt)
    for (int i = tid; i < DDIM * TM / 4; i += NTHREADS) {
        int d = i >> 4, c = i & 15;
        float4 v = *(const float4*)(xt + (size_t)d * T + t0 + c * 4);
        *(float4*)(Xs + d * TM + c * 4) = v;
    }
    __syncthreads();

    // Per-token ||x||^2, sequential over d ascending (ref-like)
    if (tid < TM) {
        float s = 0.f;
        for (int d = 0; d < DDIM; ++d) {
            float v = Xs[d * TM + tid];
            s = __fadd_rn(s, __fmul_rn(v, v));
        }
        s_xsq[tid] = s;
    }
    __syncthreads();

    float xsq[4];
#pragma unroll
    for (int j = 0; j < 4; ++j) xsq[j] = s_xsq[ty * 4 + j];

    float bv[4];
    int   bi[4];
#pragma unroll
    for (int j = 0; j < 4; ++j) { bv[j] = -3.4e38f; bi[j] = 0; }

    for (int k0 = 0; k0 < K; k0 += KT) {
        // Load E chunk (coalesced from pre-transposed g_et)
        for (int i = tid; i < DDIM * KT / 4; i += NTHREADS) {
            int d = i >> 4, c = i & 15;
            float4 v = *(const float4*)(et + (size_t)d * K + k0 + c * 4);
            *(float4*)(Es + d * KT + c * 4) = v;
        }
        __syncthreads();

        float acc[4][4];
#pragma unroll
        for (int a = 0; a < 4; ++a)
#pragma unroll
            for (int b = 0; b < 4; ++b) acc[a][b] = 0.f;

#pragma unroll 8
        for (int d = 0; d < DDIM; ++d) {
            float4 av = *(const float4*)(Xs + d * TM + ty * 4);
            float4 ev = *(const float4*)(Es + d * KT + tx * 4);
            float a[4] = {av.x, av.y, av.z, av.w};
            float b[4] = {ev.x, ev.y, ev.z, ev.w};
#pragma unroll
            for (int jt = 0; jt < 4; ++jt)
#pragma unroll
                for (int jk = 0; jk < 4; ++jk)
                    acc[jt][jk] = fmaf(a[jt], b[jk], acc[jt][jk]);
        }

        // Score with the reference's exact elementwise rounding:
        // dist = -((x_sq - 2*dot) + e_sq). Strictly-greater keeps earliest k.
#pragma unroll
        for (int jk = 0; jk < 4; ++jk) {
            int kg = k0 + tx * 4 + jk;
            float es = __ldg(esq + kg);
#pragma unroll
            for (int jt = 0; jt < 4; ++jt) {
                float v1 = __fsub_rn(xsq[jt], __fmul_rn(2.0f, acc[jt][jk]));
                float v2 = __fadd_rn(v1, es);
                float dn = -v2;
                if (dn > bv[jt]) { bv[jt] = dn; bi[jt] = kg; }
            }
        }
        __syncthreads();  // before next chunk overwrites Es
    }

    // Reduce across the 16 lanes sharing each token row (half-warp shuffles).
    // Ties -> lowest index (jnp.argmax semantics).
#pragma unroll
    for (int jt = 0; jt < 4; ++jt) {
        float v = bv[jt];
        int   ii = bi[jt];
#pragma unroll
        for (int off = 8; off > 0; off >>= 1) {
            float ov = __shfl_down_sync(0xffffffffu, v, off, 16);
            int   oi = __shfl_down_sync(0xffffffffu, ii, off, 16);
            if (ov > v || (ov == v && oi < ii)) { v = ov; ii = oi; }
        }
        if (tx == 0) s_bi[ty * 4 + jt] = ii;
    }
    __syncthreads();

    // Outputs: indices (as float) + gathered codebook rows (coalesced float4)
    if (out_i && tid < TM) out_i[t0 + tid] = (float)s_bi[tid];
    for (int i = tid; i < TM * DDIM / 4; i += NTHREADS) {
        int t = i >> 6, q = i & 63;
        int kb = s_bi[t];
        float4 v = *(const float4*)(embed + (size_t)kb * DDIM + q * 4);
        *(float4*)(out_q + (size_t)(t0 + t) * DDIM + q * 4) = v;
    }
}

// ---------------------------------------------------------------------------
extern "C" void kernel_launch(void* const* d_in, const int* in_sizes, int n_in,
                              void* d_out, int out_size) {
    const float* x     = (const float*)d_in[0];
    const float* embed = (const float*)d_in[1];
    // d_in[2] = node_mask (all-ones; does not affect returned outputs)

    int T  = in_sizes[2];             // B*N = 32768
    int Dd = in_sizes[0] / T;         // 256
    int K  = in_sizes[1] / Dd;        // 4096
    (void)Dd;

    float* outq = (float*)d_out;
    float* outi = nullptr;
    if ((long long)out_size >= (long long)T * DDIM + T)
        outi = outq + (size_t)T * DDIM;

    float* p_esq; float* p_et; float* p_xt;
    cudaGetSymbolAddress((void**)&p_esq, g_esq);
    cudaGetSymbolAddress((void**)&p_et,  g_et);
    cudaGetSymbolAddress((void**)&p_xt,  g_xt);

    // Prep: ||e||^2, transposed embed, transposed x
    esq_kernel<<<(K + 255) / 256, 256>>>(embed, K);
    {
        dim3 grd(DDIM / 32, K / 32), blk(32, 8);
        transpose_kernel<<<grd, blk>>>(embed, p_et, K, DDIM);
    }
    {
        dim3 grd(DDIM / 32, T / 32), blk(32, 8);
        transpose_kernel<<<grd, blk>>>(x, p_xt, T, DDIM);
    }

    size_t smem = (size_t)(2 * DDIM * TM) * sizeof(float) + TM * sizeof(float) + TM * sizeof(int);
    cudaFuncSetAttribute(vq_argmax_kernel,
                         cudaFuncAttributeMaxDynamicSharedMemorySize, (int)smem);
    vq_argmax_kernel<<<T / TM, NTHREADS, smem>>>(p_xt, p_et, p_esq, embed,
                                                 outq, outi, T, K);
}

// round 3
// speedup vs baseline: 3.2858x; 3.2858x over previous
#include <cuda_runtime.h>
#include <cstdint>
#include <cfloat>

// Shapes fixed by dataset: T=32768 tokens, K=4096 codes, D=256.
#define T_TOK 32768
#define K_COD 4096
#define D_DIM 256
#define EPS_GAP 0.01f

// Main-kernel tiling: CTA = 128 tokens x 128 codes/chunk, 32 chunks, D in 4
// sub-chunks of 64. 8 warps = 4(M) x 2(N); warp tile 32 tok x 64 codes.
#define A_OFF   0        // A fragments: 8 mt x 32 kt x 32 lanes x 16B = 128KB
#define B_OFF   131072   // B ring: 2 x 32KB  ([kt8][nt16][lane][8B])
#define ESQ_OFF 196608   // 16KB
#define SMEM_BYTES 212992

// Scratch (__device__ globals; no allocs allowed)
__device__ uint4  g_at[(size_t)256 * 8192];     // 32MB: [cta][mt][kt][lane] a0..a3
__device__ uint2  g_bt[(size_t)32 * 4 * 4096];  // 4MB:  [nc][kc][kt][nt][lane] b0,b1
__device__ float  g_esq[K_COD];
__device__ float  g_cval[(size_t)T_TOK * 32];
__device__ int    g_cidx[(size_t)T_TOK * 32];

static __device__ __forceinline__ uint32_t smem_u32(const void* p) {
    uint32_t a;
    asm("{ .reg .u64 t; cvta.to.shared.u64 t, %1; cvt.u32.u64 %0, t; }"
        : "=r"(a) : "l"(p));
    return a;
}
static __device__ __forceinline__ uint32_t f2tf(float f) {
    uint32_t r; asm("cvt.rna.tf32.f32 %0, %1;" : "=r"(r) : "f"(f)); return r;
}
static __device__ __forceinline__ void cp16(uint32_t dst, const void* src) {
    asm volatile("cp.async.cg.shared.global [%0], [%1], 16;"
                 :: "r"(dst), "l"(__cvta_generic_to_global(src)) : "memory");
}
#define CP_COMMIT() asm volatile("cp.async.commit_group;" ::: "memory")
#define CP_WAIT(n)  asm volatile("cp.async.wait_group %0;" :: "n"(n) : "memory")

static __device__ __forceinline__ void mma8(float& d0, float& d1, float& d2, float& d3,
                                            uint4 a, uint2 b) {
    asm volatile(
        "mma.sync.aligned.m16n8k8.row.col.f32.tf32.tf32.f32 "
        "{%0,%1,%2,%3}, {%4,%5,%6,%7}, {%8,%9}, {%0,%1,%2,%3};"
        : "+f"(d0), "+f"(d1), "+f"(d2), "+f"(d3)
        : "r"(a.x), "r"(a.y), "r"(a.z), "r"(a.w), "r"(b.x), "r"(b.y));
}

// ---------------------------------------------------------------------------
__global__ void esq_kernel(const float* __restrict__ embed) {
    int k = blockIdx.x * blockDim.x + threadIdx.x;
    const float* row = embed + (size_t)k * D_DIM;
    float s = 0.f;
    for (int d = 0; d < D_DIM; ++d)
        s = __fadd_rn(s, __fmul_rn(row[d], row[d]));
    g_esq[k] = s;
}

// Pack x -> tf32 A fragments. unit u = [cta(256)][mtile(8)][ktile(32)][lane(32)]
// a0=(r,c) a1=(r+8,c) a2=(r,c+4) a3=(r+8,c+4); r=mtile*16+lane/4, c=ktile*8+lane%4
__global__ void pack_a_kernel(const float* __restrict__ x) {
    uint32_t u = blockIdx.x * 256 + threadIdx.x;
    int cta = u >> 13, r = u & 8191;
    int mtile = r >> 10, kt = (r >> 5) & 31, lane = r & 31;
    int row = cta * 128 + mtile * 16 + (lane >> 2);
    int col = kt * 8 + (lane & 3);
    const float* x0 = x + (size_t)row * D_DIM + col;
    const float* x8 = x0 + 8 * D_DIM;
    uint4 q;
    q.x = f2tf(x0[0]); q.y = f2tf(x8[0]); q.z = f2tf(x0[4]); q.w = f2tf(x8[4]);
    g_at[u] = q;
}

// Pack embed -> tf32 B fragments. unit u = [nc(32)][kc(4)][kt(8)][nt(16)][lane]
// b0 = E[n][k], b1 = E[n][k+4]; n = nc*128+nt*8+lane/4, k = kc*64+kt*8+lane%4
__global__ void pack_b_kernel(const float* __restrict__ embed) {
    uint32_t u = blockIdx.x * 256 + threadIdx.x;
    int nc = u >> 14, r = u & 16383;
    int kc = r >> 12, kt = (r >> 9) & 7, nt = (r >> 5) & 15, lane = r & 31;
    int n = nc * 128 + nt * 8 + (lane >> 2);
    int k = kc * 64 + kt * 8 + (lane & 3);
    const float* e = embed + (size_t)n * D_DIM + k;
    uint2 q;
    q.x = f2tf(e[0]); q.y = f2tf(e[4]);
    g_bt[u] = q;
}

// ---------------------------------------------------------------------------
// Main: tf32 GEMM scores + per-lane top-4 candidate tracking.
__global__ __launch_bounds__(256, 1) void vq_mma_kernel() {
    extern __shared__ char sm[];
    const uint32_t sb = smem_u32(sm);
    const int tid = threadIdx.x, lane = tid & 31, wid = tid >> 5;
    const int warpM = wid & 3, warpN = wid >> 2;
    const int cta = blockIdx.x;

    // Prologue copies: A (128KB), esq (16KB), B chunk 0 (32KB)
    {
        const uint4* as = g_at + (size_t)cta * 8192;
#pragma unroll
        for (int i = 0; i < 32; ++i)
            cp16(sb + A_OFF + (uint32_t)(i * 256 + tid) * 16, as + i * 256 + tid);
        const uint4* es = (const uint4*)g_esq;
#pragma unroll
        for (int i = 0; i < 4; ++i)
            cp16(sb + ESQ_OFF + (uint32_t)(i * 256 + tid) * 16, es + i * 256 + tid);
        const uint4* bs = (const uint4*)g_bt;
#pragma unroll
        for (int i = 0; i < 8; ++i)
            cp16(sb + B_OFF + (uint32_t)(i * 256 + tid) * 16, bs + i * 256 + tid);
        CP_COMMIT();
    }

    float acc[2][8][4];
#pragma unroll
    for (int mt = 0; mt < 2; ++mt)
#pragma unroll
        for (int nt = 0; nt < 8; ++nt)
#pragma unroll
            for (int c = 0; c < 4; ++c) acc[mt][nt][c] = 0.f;

    float tv[4][4];
    int   ti[4][4];
#pragma unroll
    for (int s = 0; s < 4; ++s)
#pragma unroll
        for (int j = 0; j < 4; ++j) { tv[s][j] = -FLT_MAX; ti[s][j] = 0; }

    for (int g = 0; g < 128; ++g) {
        if (g + 1 < 128) {
            const uint4* bs = (const uint4*)g_bt + (size_t)(g + 1) * 2048;
            uint32_t bd = sb + B_OFF + (uint32_t)((g + 1) & 1) * 32768;
#pragma unroll
            for (int i = 0; i < 8; ++i)
                cp16(bd + (uint32_t)(i * 256 + tid) * 16, bs + i * 256 + tid);
            CP_COMMIT();
            CP_WAIT(1);
        } else {
            CP_COMMIT();
            CP_WAIT(0);
        }
        __syncthreads();

        const char* bbuf = sm + B_OFF + (g & 1) * 32768;
#pragma unroll
        for (int kk = 0; kk < 8; ++kk) {
            int ktile = (g & 3) * 8 + kk;
            uint4 a[2];
#pragma unroll
            for (int mt = 0; mt < 2; ++mt)
                a[mt] = *(const uint4*)(sm + A_OFF +
                        (size_t)(((warpM * 2 + mt) * 32 + ktile) * 32 + lane) * 16);
#pragma unroll
            for (int nt = 0; nt < 8; ++nt) {
                uint2 b = *(const uint2*)(bbuf +
                        (size_t)((kk * 16 + warpN * 8 + nt) * 32 + lane) * 8);
#pragma unroll
                for (int mt = 0; mt < 2; ++mt)
                    mma8(acc[mt][nt][0], acc[mt][nt][1], acc[mt][nt][2], acc[mt][nt][3],
                         a[mt], b);
            }
        }

        if ((g & 3) == 3) {
            // Epilogue: chunk nc complete. score = 2*dot - esq (xsq cancels).
            int nc = g >> 2;
            int n0 = nc * 128 + warpN * 64 + 2 * (lane & 3);
            const float* esm = (const float*)(sm + ESQ_OFF);
#pragma unroll
            for (int mt = 0; mt < 2; ++mt)
#pragma unroll
                for (int nt = 0; nt < 8; ++nt)
#pragma unroll
                    for (int c = 0; c < 4; ++c) {
                        int n = n0 + nt * 8 + (c & 1);
                        float v = 2.f * acc[mt][nt][c] - esm[n];
                        acc[mt][nt][c] = 0.f;
                        const int s = mt * 2 + (c >> 1);
                        if (v > tv[s][3]) {
                            if (v > tv[s][2]) {
                                tv[s][3] = tv[s][2]; ti[s][3] = ti[s][2];
                                if (v > tv[s][1]) {
                                    tv[s][2] = tv[s][1]; ti[s][2] = ti[s][1];
                                    if (v > tv[s][0]) {
                                        tv[s][1] = tv[s][0]; ti[s][1] = ti[s][0];
                                        tv[s][0] = v; ti[s][0] = n;
                                    } else { tv[s][1] = v; ti[s][1] = n; }
                                } else { tv[s][2] = v; ti[s][2] = n; }
                            } else { tv[s][3] = v; ti[s][3] = n; }
                        }
                    }
        }
        __syncthreads();
    }

    // Write 4 candidates per (token, source). Sources: warpN(2) x (lane&3)(4) x 4
#pragma unroll
    for (int s = 0; s < 4; ++s) {
        int row = warpM * 32 + (s >> 1) * 16 + (s & 1) * 8 + (lane >> 2);
        size_t base = ((size_t)cta * 128 + row) * 32 + warpN * 16 + (lane & 3) * 4;
#pragma unroll
        for (int j = 0; j < 4; ++j) {
            g_cval[base + j] = tv[s][j];
            g_cidx[base + j] = ti[s][j];
        }
    }
}

// ---------------------------------------------------------------------------
// Merge + (rare) exact rescore + gather. One warp per token.
__global__ __launch_bounds__(256) void merge_kernel(const float* __restrict__ x,
                                                    const float* __restrict__ embed,
                                                    float* __restrict__ out_q,
                                                    float* __restrict__ out_i) {
    const int lane = threadIdx.x & 31, wid = threadIdx.x >> 5;
    const int t = blockIdx.x * 8 + wid;

    float v = g_cval[(size_t)t * 32 + lane];
    int   i = g_cidx[(size_t)t * 32 + lane];

    // approx argmax, tie -> lowest index
    float v1 = v; int i1 = i;
#pragma unroll
    for (int off = 16; off > 0; off >>= 1) {
        float ov = __shfl_xor_sync(0xffffffffu, v1, off);
        int   oi = __shfl_xor_sync(0xffffffffu, i1, off);
        if (ov > v1 || (ov == v1 && oi < i1)) { v1 = ov; i1 = oi; }
    }
    // runner-up (candidate codes are pairwise distinct by construction)
    float w = (i == i1) ? -FLT_MAX : v;
#pragma unroll
    for (int off = 16; off > 0; off >>= 1) {
        float ow = __shfl_xor_sync(0xffffffffu, w, off);
        if (ow > w) w = ow;
    }

    int best = i1;
    if (!(v1 - w >= EPS_GAP)) {
        // Exact fp32 rescore of all 32 candidates, ref-faithful rounding.
        const float* xr = x + (size_t)t * D_DIM;
        float p = 0.f;
#pragma unroll
        for (int j = 0; j < 8; ++j) {
            float xv = xr[lane + 32 * j];
            p = __fadd_rn(p, __fmul_rn(xv, xv));
        }
#pragma unroll
        for (int off = 16; off > 0; off >>= 1)
            p = __fadd_rn(p, __shfl_xor_sync(0xffffffffu, p, off));
        const float xsq = p;

        const float* er = embed + (size_t)i * D_DIM;
        float dot = 0.f;
        for (int d = 0; d < D_DIM; ++d)
            dot = fmaf(xr[d], er[d], dot);
        float t2 = __fsub_rn(xsq, __fmul_rn(2.f, dot));
        float dn = -__fadd_rn(t2, g_esq[i]);

        float bv = dn; int bi = i;
#pragma unroll
        for (int off = 16; off > 0; off >>= 1) {
            float ov = __shfl_xor_sync(0xffffffffu, bv, off);
            int   oi = __shfl_xor_sync(0xffffffffu, bi, off);
            if (ov > bv || (ov == bv && oi < bi)) { bv = ov; bi = oi; }
        }
        best = bi;
    }

    // Gather + index output
    const float4* src = (const float4*)(embed + (size_t)best * D_DIM);
    float4* dst = (float4*)(out_q + (size_t)t * D_DIM);
    dst[lane] = src[lane];
    dst[lane + 32] = src[lane + 32];
    if (lane == 0 && out_i) out_i[t] = (float)best;
}

// ---------------------------------------------------------------------------
extern "C" void kernel_launch(void* const* d_in, const int* in_sizes, int n_in,
                              void* d_out, int out_size) {
    const float* x     = (const float*)d_in[0];
    const float* embed = (const float*)d_in[1];

    int T = in_sizes[2];  // 32768

    float* outq = (float*)d_out;
    float* outi = nullptr;
    if ((long long)out_size >= (long long)T * D_DIM + T)
        outi = outq + (size_t)T * D_DIM;

    esq_kernel<<<K_COD / 256, 256>>>(embed);
    pack_b_kernel<<<(32 * 4 * 4096) / 256, 256>>>(embed);
    pack_a_kernel<<<(256 * 8192) / 256, 256>>>(x);

    cudaFuncSetAttribute(vq_mma_kernel,
                         cudaFuncAttributeMaxDynamicSharedMemorySize, SMEM_BYTES);
    vq_mma_kernel<<<T / 128, 256, SMEM_BYTES>>>();

    merge_kernel<<<T / 8, 256>>>(x, embed, outq, outi);
}

// round 4
// speedup vs baseline: 6.5429x; 1.9913x over previous
#include <cuda_runtime.h>
#include <cuda_fp16.h>
#include <cstdint>
#include <cfloat>

// Shapes fixed by dataset: T=32768 tokens, K=4096 codes, D=256.
#define T_TOK 32768
#define K_COD 4096
#define D_DIM 256
#define EPS_GAP 0.01f

// Main kernel: CTA = 128 tokens x full K. N chunk 128 codes, k-stage 128 deep
// (8 HMMA k16 steps). 64 stages total (32 chunks x 2). 8 warps = 4(M) x 2(N).
#define A_OFF   0        // A frags fp16: [mtile8][ktile16][lane] uint4 = 64KB
#define B_OFF   65536    // ring: 4 stages x 32KB ([kk8][np8][lane] uint4)
#define ESQ_OFF 196608   // 16KB
#define SMEM_BYTES 212992

__device__ uint4  g_at[(size_t)256 * 4096];   // 16MB packed A fragments
__device__ uint4  g_bt[(size_t)64 * 2048];    // 2MB packed B fragments
__device__ float  g_esq[K_COD];
__device__ float  g_cval[(size_t)T_TOK * 16];
__device__ int    g_cidx[(size_t)T_TOK * 16];

static __device__ __forceinline__ uint32_t smem_u32(const void* p) {
    uint32_t a;
    asm("{ .reg .u64 t; cvta.to.shared.u64 t, %1; cvt.u32.u64 %0, t; }"
        : "=r"(a) : "l"(p));
    return a;
}
static __device__ __forceinline__ void cp16(uint32_t dst, const void* src) {
    asm volatile("cp.async.cg.shared.global [%0], [%1], 16;"
                 :: "r"(dst), "l"(__cvta_generic_to_global(src)) : "memory");
}
#define CP_COMMIT() asm volatile("cp.async.commit_group;" ::: "memory")
#define CP_WAIT(n)  asm volatile("cp.async.wait_group %0;" :: "n"(n) : "memory")

static __device__ __forceinline__ void mma16(float& d0, float& d1, float& d2, float& d3,
                                             uint4 a, uint32_t b0, uint32_t b1) {
    asm volatile(
        "mma.sync.aligned.m16n8k16.row.col.f32.f16.f16.f32 "
        "{%0,%1,%2,%3}, {%4,%5,%6,%7}, {%8,%9}, {%0,%1,%2,%3};"
        : "+f"(d0), "+f"(d1), "+f"(d2), "+f"(d3)
        : "r"(a.x), "r"(a.y), "r"(a.z), "r"(a.w), "r"(b0), "r"(b1));
}
static __device__ __forceinline__ uint32_t h2pack(float a, float b) {
    __half2 h = __floats2half2_rn(a, b);
    return *(uint32_t*)&h;
}

// ---------------------------------------------------------------------------
__global__ void esq_kernel(const float* __restrict__ embed) {
    int k = blockIdx.x * blockDim.x + threadIdx.x;
    const float* row = embed + (size_t)k * D_DIM;
    float s = 0.f;
    for (int d = 0; d < D_DIM; ++d)
        s = __fadd_rn(s, __fmul_rn(row[d], row[d]));
    g_esq[k] = s;
}

// Pack x -> fp16 A fragments (m16n8k16 layout).
// unit u = [cta(256)][mtile(8)][ktile16(16)][lane(32)] -> uint4 {a0,a1,a2,a3}
// a0={A[r][c],A[r][c+1]} a1={A[r+8][c],..} a2={A[r][c+8],..} a3={A[r+8][c+8],..}
// r = mtile*16 + lane/4, c = ktile*16 + (lane%4)*2
__global__ void pack_a_kernel(const float* __restrict__ x) {
    uint32_t u = blockIdx.x * 256 + threadIdx.x;
    int cta = u >> 12, r = u & 4095;
    int mtile = r >> 9, kt = (r >> 5) & 15, lane = r & 31;
    int row = cta * 128 + mtile * 16 + (lane >> 2);
    int col = kt * 16 + (lane & 3) * 2;
    const float* x0 = x + (size_t)row * D_DIM + col;
    const float* x8 = x0 + 8 * D_DIM;
    uint4 q;
    q.x = h2pack(x0[0], x0[1]);
    q.y = h2pack(x8[0], x8[1]);
    q.z = h2pack(x0[8], x0[9]);
    q.w = h2pack(x8[8], x8[9]);
    g_at[u] = q;
}

// Pack embed -> fp16 B fragments, paired for LDS.128.
// unit u = [stage(64)][kk(8)][np(8)][lane(32)] -> uint4 {b0(n0),b1(n0),b0(n1),b1(n1)}
// stage s: nc = s/2, half = s%2; np = warpN*4 + ntp, nt = 2*ntp + {0,1}
// code n = nc*128 + warpN*64 + nt*8 + lane/4; k = half*128 + kk*16 + (lane%4)*2
// b0 = {E[n][k], E[n][k+1]}, b1 = {E[n][k+8], E[n][k+9]}
__global__ void pack_b_kernel(const float* __restrict__ embed) {
    uint32_t u = blockIdx.x * 256 + threadIdx.x;
    int s = u >> 11, r = u & 2047;
    int kk = r >> 8, np = (r >> 5) & 7, lane = r & 31;
    int nc = s >> 1, half = s & 1;
    int warpN = np >> 2, ntp = np & 3;
    int k = half * 128 + kk * 16 + (lane & 3) * 2;
    int n0 = nc * 128 + warpN * 64 + (2 * ntp) * 8 + (lane >> 2);
    const float* e0 = embed + (size_t)n0 * D_DIM + k;
    const float* e1 = e0 + 8 * D_DIM;   // nt+1 -> n += 8
    uint4 q;
    q.x = h2pack(e0[0], e0[1]);
    q.y = h2pack(e0[8], e0[9]);
    q.z = h2pack(e1[0], e1[1]);
    q.w = h2pack(e1[8], e1[9]);
    g_bt[u] = q;
}

// ---------------------------------------------------------------------------
// Main: fp16 GEMM scores + branchless per-source top-2 candidates.
__global__ __launch_bounds__(256, 1) void vq_mma_kernel() {
    extern __shared__ char sm[];
    const uint32_t sb = smem_u32(sm);
    const int tid = threadIdx.x, lane = tid & 31, wid = tid >> 5;
    const int warpM = wid & 3, warpN = wid >> 2;
    const int cta = blockIdx.x;

    // Prologue: A (64KB) + esq (16KB) + stage0 | stage1 | stage2
    {
        const uint4* as = g_at + (size_t)cta * 4096;
#pragma unroll
        for (int i = 0; i < 16; ++i)
            cp16(sb + A_OFF + (uint32_t)(i * 256 + tid) * 16, as + i * 256 + tid);
        const uint4* es = (const uint4*)g_esq;
#pragma unroll
        for (int i = 0; i < 4; ++i)
            cp16(sb + ESQ_OFF + (uint32_t)(i * 256 + tid) * 16, es + i * 256 + tid);
#pragma unroll
        for (int i = 0; i < 8; ++i)
            cp16(sb + B_OFF + (uint32_t)(i * 256 + tid) * 16, g_bt + i * 256 + tid);
        CP_COMMIT();
#pragma unroll
        for (int i = 0; i < 8; ++i)
            cp16(sb + B_OFF + 32768 + (uint32_t)(i * 256 + tid) * 16,
                 g_bt + 2048 + i * 256 + tid);
        CP_COMMIT();
#pragma unroll
        for (int i = 0; i < 8; ++i)
            cp16(sb + B_OFF + 65536 + (uint32_t)(i * 256 + tid) * 16,
                 g_bt + 4096 + i * 256 + tid);
        CP_COMMIT();
    }

    float acc[2][8][4];
#pragma unroll
    for (int mt = 0; mt < 2; ++mt)
#pragma unroll
        for (int nt = 0; nt < 8; ++nt)
#pragma unroll
            for (int c = 0; c < 4; ++c) acc[mt][nt][c] = 0.f;

    float t1[4], t2[4];
    int   i1[4], i2[4];
#pragma unroll
    for (int s = 0; s < 4; ++s) {
        t1[s] = -FLT_MAX; t2[s] = -FLT_MAX; i1[s] = 0; i2[s] = 0;
    }

    const float* esm = (const float*)(sm + ESQ_OFF);

    for (int g = 0; g < 64; ++g) {
        CP_WAIT(2);
        __syncthreads();
        // Prefetch stage g+3 (empty commit keeps group accounting uniform)
        if (g + 3 < 64) {
            const uint4* bs = g_bt + (size_t)(g + 3) * 2048;
            uint32_t bd = sb + B_OFF + (uint32_t)((g + 3) & 3) * 32768;
#pragma unroll
            for (int i = 0; i < 8; ++i)
                cp16(bd + (uint32_t)(i * 256 + tid) * 16, bs + i * 256 + tid);
        }
        CP_COMMIT();

        const char* bbuf = sm + B_OFF + (g & 3) * 32768;
#pragma unroll
        for (int kk = 0; kk < 8; ++kk) {
            int ktile = (g & 1) * 8 + kk;
            uint4 a0 = *(const uint4*)(sm + A_OFF +
                       (size_t)(((warpM * 2 + 0) * 16 + ktile) * 32 + lane) * 16);
            uint4 a1 = *(const uint4*)(sm + A_OFF +
                       (size_t)(((warpM * 2 + 1) * 16 + ktile) * 32 + lane) * 16);
#pragma unroll
            for (int ntp = 0; ntp < 4; ++ntp) {
                uint4 bq = *(const uint4*)(bbuf +
                           (size_t)((kk * 8 + warpN * 4 + ntp) * 32 + lane) * 16);
                int ne = 2 * ntp, no = 2 * ntp + 1;
                mma16(acc[0][ne][0], acc[0][ne][1], acc[0][ne][2], acc[0][ne][3], a0, bq.x, bq.y);
                mma16(acc[1][ne][0], acc[1][ne][1], acc[1][ne][2], acc[1][ne][3], a1, bq.x, bq.y);
                mma16(acc[0][no][0], acc[0][no][1], acc[0][no][2], acc[0][no][3], a0, bq.z, bq.w);
                mma16(acc[1][no][0], acc[1][no][1], acc[1][no][2], acc[1][no][3], a1, bq.z, bq.w);
            }
        }

        if (g & 1) {
            // Chunk nc done: score = 2*dot - esq (xsq constant per token).
            int nc = g >> 1;
            int n0 = nc * 128 + warpN * 64 + (lane & 3) * 2;
#pragma unroll
            for (int mt = 0; mt < 2; ++mt)
#pragma unroll
                for (int nt = 0; nt < 8; ++nt)
#pragma unroll
                    for (int c = 0; c < 4; ++c) {
                        int n = n0 + nt * 8 + (c & 1);
                        float v = 2.f * acc[mt][nt][c] - esm[n];
                        acc[mt][nt][c] = 0.f;
                        const int s = mt * 2 + (c >> 1);
                        // branchless ordered top-2 (ties keep earlier = lower n)
                        bool gt1 = v > t1[s];
                        bool gt2 = v > t2[s];
                        i2[s] = gt1 ? i1[s] : (gt2 ? n : i2[s]);
                        t2[s] = gt1 ? t1[s] : (gt2 ? v : t2[s]);
                        i1[s] = gt1 ? n : i1[s];
                        t1[s] = gt1 ? v : t1[s];
                    }
        }
        __syncthreads();
    }

    // Write candidates: 8 sources x top-2 per token.
#pragma unroll
    for (int s = 0; s < 4; ++s) {
        int row = warpM * 32 + (s >> 1) * 16 + (s & 1) * 8 + (lane >> 2);
        size_t base = ((size_t)cta * 128 + row) * 16 + (warpN * 4 + (lane & 3)) * 2;
        g_cval[base + 0] = t1[s]; g_cidx[base + 0] = i1[s];
        g_cval[base + 1] = t2[s]; g_cidx[base + 1] = i2[s];
    }
}

// ---------------------------------------------------------------------------
// Merge + rare exact rescore + gather. One warp per token (16 candidates).
__global__ __launch_bounds__(256) void merge_kernel(const float* __restrict__ x,
                                                    const float* __restrict__ embed,
                                                    float* __restrict__ out_q,
                                                    float* __restrict__ out_i) {
    const int lane = threadIdx.x & 31, wid = threadIdx.x >> 5;
    const int t = blockIdx.x * 8 + wid;

    float v = -FLT_MAX;
    int   i = 0x7fffffff;
    if (lane < 16) {
        v = g_cval[(size_t)t * 16 + lane];
        i = g_cidx[(size_t)t * 16 + lane];
    }

    float v1 = v; int i1 = i;
#pragma unroll
    for (int off = 16; off > 0; off >>= 1) {
        float ov = __shfl_xor_sync(0xffffffffu, v1, off);
        int   oi = __shfl_xor_sync(0xffffffffu, i1, off);
        if (ov > v1 || (ov == v1 && oi < i1)) { v1 = ov; i1 = oi; }
    }
    float w = (i == i1) ? -FLT_MAX : v;
#pragma unroll
    for (int off = 16; off > 0; off >>= 1) {
        float ow = __shfl_xor_sync(0xffffffffu, w, off);
        if (ow > w) w = ow;
    }

    int best = i1;
    if (!(v1 - w >= EPS_GAP)) {
        // Exact fp32 rescore of the 16 candidates, ref-faithful rounding.
        const float* xr = x + (size_t)t * D_DIM;
        float p = 0.f;
#pragma unroll
        for (int j = 0; j < 8; ++j) {
            float xv = xr[lane + 32 * j];
            p = __fadd_rn(p, __fmul_rn(xv, xv));
        }
#pragma unroll
        for (int off = 16; off > 0; off >>= 1)
            p = __fadd_rn(p, __shfl_xor_sync(0xffffffffu, p, off));
        const float xsq = p;

        float dn = -FLT_MAX;
        if (lane < 16) {
            const float* er = embed + (size_t)i * D_DIM;
            float dot = 0.f;
            for (int d = 0; d < D_DIM; ++d)
                dot = fmaf(xr[d], er[d], dot);
            float t2v = __fsub_rn(xsq, __fmul_rn(2.f, dot));
            dn = -__fadd_rn(t2v, g_esq[i]);
        }
        float bv = dn; int bi = i;
#pragma unroll
        for (int off = 16; off > 0; off >>= 1) {
            float ov = __shfl_xor_sync(0xffffffffu, bv, off);
            int   oi = __shfl_xor_sync(0xffffffffu, bi, off);
            if (ov > bv || (ov == bv && oi < bi)) { bv = ov; bi = oi; }
        }
        best = bi;
    }

    const float4* src = (const float4*)(embed + (size_t)best * D_DIM);
    float4* dst = (float4*)(out_q + (size_t)t * D_DIM);
    dst[lane] = src[lane];
    dst[lane + 32] = src[lane + 32];
    if (lane == 0 && out_i) out_i[t] = (float)best;
}

// ---------------------------------------------------------------------------
extern "C" void kernel_launch(void* const* d_in, const int* in_sizes, int n_in,
                              void* d_out, int out_size) {
    const float* x     = (const float*)d_in[0];
    const float* embed = (const float*)d_in[1];

    int T = in_sizes[2];  // 32768

    float* outq = (float*)d_out;
    float* outi = nullptr;
    if ((long long)out_size >= (long long)T * D_DIM + T)
        outi = outq + (size_t)T * D_DIM;

    esq_kernel<<<K_COD / 256, 256>>>(embed);
    pack_b_kernel<<<(64 * 2048) / 256, 256>>>(embed);
    pack_a_kernel<<<(256 * 4096) / 256, 256>>>(x);

    cudaFuncSetAttribute(vq_mma_kernel,
                         cudaFuncAttributeMaxDynamicSharedMemorySize, SMEM_BYTES);
    vq_mma_kernel<<<T / 128, 256, SMEM_BYTES>>>();

    merge_kernel<<<T / 8, 256>>>(x, embed, outq, outi);
}